// round 16
// baseline (speedup 1.0000x reference)
#include <cuda_runtime.h>
#include <cuda_bf16.h>

// SimpleLSTM: B=64, T=2048, H=512.
// Persistent kernel: 128 CTAs = 4 batch-groups x 32 hidden-groups, 256 threads.
// W_hh slice in SMEM (row-permuted, conflict-free), c in registers.
// Fine-grained sync: per-CTA publish flags; warp w waits only on its 4
// producers (gh=4w..4w+3), quarter-pipelined wait->LDG->STS->GEMM so staging
// latency and producer skew hide under compute. Fused FC head.

#define B_    64
#define T_    2048
#define H_    512
#define NCTA  128
#define NTHR  256
#define BS_   16
#define HS_   16
#define ROWS  64

#define OFF_W    0            // [512][64]    32768 floats (128 KB), row-permuted
#define OFF_H    32768        // [512][16]     8192 floats (32 KB)
#define OFF_RED  40960        // [8][8][64]f2  8192 floats (32 KB)
#define SMEM_FLOATS 49152
#define SMEM_BYTES  (SMEM_FLOATS * 4)

#define FLAGSTR 8             // 32B stride between flags
#define NFLAGS  ((T_ + 1) * 4 * 32 * FLAGSTR)

__device__ float    g_hall[(size_t)T_ * H_ * B_];
__device__ unsigned g_done[NFLAGS];

typedef unsigned long long ull;

__device__ __forceinline__ ull dup2(float x) {
    ull r; unsigned u = __float_as_uint(x);
    asm("mov.b64 %0, {%1, %1};" : "=l"(r) : "r"(u));
    return r;
}
__device__ __forceinline__ void fma2(ull& d, ull a, ull b) {
    asm("fma.rn.f32x2 %0, %1, %2, %0;" : "+l"(d) : "l"(a), "l"(b));
}
__device__ __forceinline__ float sigm(float x) {
    return __fdividef(1.0f, 1.0f + __expf(-x));
}
__device__ __forceinline__ float tanh_f(float x) {
    return __fdividef(2.0f, 1.0f + __expf(-2.0f * x)) - 1.0f;
}
__device__ __forceinline__ unsigned ld_acq(const unsigned* p) {
    unsigned v;
    asm volatile("ld.acquire.gpu.global.u32 %0, [%1];" : "=r"(v) : "l"(p) : "memory");
    return v;
}

__global__ void lstm_init_kernel() {
    int i = blockIdx.x * blockDim.x + threadIdx.x;
    if (i < NFLAGS) g_done[i] = 0u;
}

__global__ void __launch_bounds__(NTHR, 1)
lstm_persistent_kernel(const float* __restrict__ x,
                       const float* __restrict__ W_ih,
                       const float* __restrict__ W_hh,
                       const float* __restrict__ b_ih,
                       const float* __restrict__ b_hh,
                       const float* __restrict__ W_fc,
                       const float* __restrict__ b_fc,
                       float* __restrict__ out) {
    extern __shared__ float sm[];
    float* sm_W    = sm + OFF_W;
    float* sm_H    = sm + OFF_H;
    ull*   sm_red  = (ull*)(sm + OFF_RED);
    float* sm_redf = sm + OFF_RED;

    const int tid   = threadIdx.x;
    const int cta   = blockIdx.x;
    const int gh    = cta >> 2;           // hidden group 0..31
    const int gb    = cta & 3;            // batch group 0..3
    const int unit0 = gh * HS_;
    const int b0    = gb * BS_;

    const int w    = tid >> 5;            // warp 0..7 -> K slice [w*64, w*64+64)
    const int lane = tid & 31;
    const int rt   = lane & 15;
    const int bg   = lane >> 4;

    const int j  = tid & 15;              // elementwise (bb, j)
    const int bb = tid >> 4;
    const int bp = bb >> 1;
    const int bc = bb & 1;

    // ---- one-time preload: W slice, slot s = rt*4+r holds local row r*16+rt ----
    for (int idx = tid; idx < ROWS * H_; idx += NTHR) {
        int s = idx >> 9;
        int k = idx & 511;
        int rl = ((s & 3) << 4) + (s >> 2);
        int G = ((rl >> 4) << 9) + unit0 + (rl & 15);
        sm_W[k * 64 + s] = W_hh[(size_t)G * H_ + k];
    }
    float wih_r[4], bias_r[4];
#pragma unroll
    for (int g = 0; g < 4; ++g) {
        int G = (g << 9) + unit0 + j;
        wih_r[g]  = __ldg(&W_ih[G]);
        bias_r[g] = __ldg(&b_ih[G]) + __ldg(&b_hh[G]);
    }
    __syncthreads();

    float c_reg = 0.0f;

    const float* Wp = sm_W + (w * 64) * 64 + rt * 4;
    const float* Hp = sm_H + (w * 64) * 16 + bg * 8;
    float* sm_Hw = sm_H + (w * 64) * 16;          // own slice [64][16]

    const float* xrow = x + (b0 + bb) * T_;
    // flags this warp waits on: producers gh = 4w+q of this batch group
    // flag index: ((t*4+gb)*32 + gh) * FLAGSTR

    for (int t = 0; t < T_; ++t) {
        float xv = __ldcg(xrow + t);

        ull acc[4][4];
#pragma unroll
        for (int r = 0; r < 4; ++r)
#pragma unroll
            for (int p = 0; p < 4; ++p) acc[r][p] = 0ull;

        if (t > 0) {
            const unsigned* fbase = g_done + ((t << 2) + gb) * 32 * FLAGSTR;
            const float* hsrc = g_hall + (size_t)(t - 1) * H_ * B_ + (size_t)(w * 64) * B_;

            float4 R0, R1;
            // wait + load quarter 0
            if (lane == 0) { while (ld_acq(fbase + (4 * w + 0) * FLAGSTR) == 0u) { } }
            __syncwarp();
            {
                int id0 = lane, id1 = lane + 32;     // chunks 0..63 of quarter 0
                R0 = __ldcg((const float4*)(hsrc + (id0 >> 2) * B_ + b0 + (id0 & 3) * 4));
                R1 = __ldcg((const float4*)(hsrc + (id1 >> 2) * B_ + b0 + (id1 & 3) * 4));
            }

#pragma unroll
            for (int q = 0; q < 4; ++q) {
                // store staged quarter q
                {
                    int id0 = lane, id1 = lane + 32;
                    int k0 = (q << 4) + (id0 >> 2);
                    int k1 = (q << 4) + (id1 >> 2);
                    *(float4*)(sm_Hw + k0 * 16 + (id0 & 3) * 4) = R0;
                    *(float4*)(sm_Hw + k1 * 16 + (id1 & 3) * 4) = R1;
                }
                // wait + issue loads for quarter q+1 (fly under GEMM q)
                if (q < 3) {
                    if (lane == 0) { while (ld_acq(fbase + (4 * w + q + 1) * FLAGSTR) == 0u) { } }
                    __syncwarp();
                    const float* hq = hsrc + (size_t)((q + 1) << 4) * B_;
                    int id0 = lane, id1 = lane + 32;
                    R0 = __ldcg((const float4*)(hq + (id0 >> 2) * B_ + b0 + (id0 & 3) * 4));
                    R1 = __ldcg((const float4*)(hq + (id1 >> 2) * B_ + b0 + (id1 & 3) * 4));
                }
                __syncwarp();

                // GEMM quarter q: kk in [16q, 16q+16)
                const float* Wq = Wp + (q << 4) * 64;
                const float* Hq = Hp + (q << 4) * 16;
#pragma unroll 4
                for (int kk = 0; kk < 16; ++kk) {
                    float4 wv = *(const float4*)(Wq + kk * 64);
                    ulonglong2 hA = *(const ulonglong2*)(Hq + kk * 16);
                    ulonglong2 hB = *(const ulonglong2*)(Hq + kk * 16 + 4);
                    ull w0 = dup2(wv.x), w1 = dup2(wv.y), w2 = dup2(wv.z), w3 = dup2(wv.w);
                    fma2(acc[0][0], w0, hA.x); fma2(acc[0][1], w0, hA.y);
                    fma2(acc[0][2], w0, hB.x); fma2(acc[0][3], w0, hB.y);
                    fma2(acc[1][0], w1, hA.x); fma2(acc[1][1], w1, hA.y);
                    fma2(acc[1][2], w1, hB.x); fma2(acc[1][3], w1, hB.y);
                    fma2(acc[2][0], w2, hA.x); fma2(acc[2][1], w2, hA.y);
                    fma2(acc[2][2], w2, hB.x); fma2(acc[2][3], w2, hB.y);
                    fma2(acc[3][0], w3, hA.x); fma2(acc[3][1], w3, hA.y);
                    fma2(acc[3][2], w3, hB.x); fma2(acc[3][3], w3, hB.y);
                }
            }
        }

        // store partials (zeros at t==0): row stride 1 across lanes, conflict-free
#pragma unroll
        for (int r = 0; r < 4; ++r)
#pragma unroll
            for (int p = 0; p < 4; ++p) {
                int row = (r << 4) + rt;
                int pp  = (bg << 2) + p;
                sm_red[w * 512 + pp * 64 + row] = acc[r][p];
            }
        __syncthreads();

        // ---- reduce 8 K-slices + cell update (thread owns (bb, j)) ----
        float gate[4];
#pragma unroll
        for (int g = 0; g < 4; ++g) {
            int row = (g << 4) + j;
            const float* rp = sm_redf + bp * 128 + row * 2 + bc;
            float s = 0.0f;
#pragma unroll
            for (int ww = 0; ww < 8; ++ww) s += rp[ww * 1024];
            gate[g] = s + xv * wih_r[g] + bias_r[g];
        }
        float ig = sigm(gate[0]);
        float fg = sigm(gate[1]);
        float gg = tanh_f(gate[2]);
        float og = sigm(gate[3]);
        c_reg = fg * c_reg + ig * gg;
        float h = og * tanh_f(c_reg);

        __stcg(&g_hall[((size_t)t * H_ + unit0 + j) * B_ + b0 + bb], h);
        if (t == T_ - 1) {
            out[B_ * T_ + (b0 + bb) * H_ + unit0 + j]           = h;      // h_n
            out[B_ * T_ + B_ * H_ + (b0 + bb) * H_ + unit0 + j] = c_reg;  // c_n
        }

        __syncthreads();
        if (tid == 0) {
            __threadfence();
            unsigned* f = g_done + ((((t + 1) << 2) + gb) * 32 + gh) * FLAGSTR;
            asm volatile("red.relaxed.gpu.global.add.u32 [%0], %1;"
                         :: "l"(f), "r"(1u) : "memory");
        }
    }

    // ================= fused FC head =================
    // wait for all 32 producers of this batch group at t = T_
    {
        const unsigned* fbase = g_done + ((T_ << 2) + gb) * 32 * FLAGSTR;
        if (tid < 32) { while (ld_acq(fbase + tid * FLAGSTR) == 0u) { } }
        __syncthreads();
    }
    for (int i = tid; i < H_; i += NTHR) sm_H[i] = __ldg(&W_fc[i]);
    __syncthreads();

    const float bfc = __ldg(&b_fc[0]);
    // this CTA: t in [gh*64, gh*64+64), batches b0..b0+15 (4 per thread)
    int tt = gh * 64 + (tid >> 2);
    int bq = b0 + (tid & 3) * 4;
    const float* hp = g_hall + (size_t)tt * H_ * B_ + bq;
    float s0 = 0.f, s1 = 0.f, s2 = 0.f, s3 = 0.f;
#pragma unroll 8
    for (int u = 0; u < H_; ++u) {
        float4 v = __ldcg((const float4*)(hp + (size_t)u * B_));
        float wf = sm_H[u];
        s0 = fmaf(v.x, wf, s0);
        s1 = fmaf(v.y, wf, s1);
        s2 = fmaf(v.z, wf, s2);
        s3 = fmaf(v.w, wf, s3);
    }
    out[(bq + 0) * T_ + tt] = s0 + bfc;
    out[(bq + 1) * T_ + tt] = s1 + bfc;
    out[(bq + 2) * T_ + tt] = s2 + bfc;
    out[(bq + 3) * T_ + tt] = s3 + bfc;
}

extern "C" void kernel_launch(void* const* d_in, const int* in_sizes, int n_in,
                              void* d_out, int out_size) {
    (void)in_sizes; (void)n_in; (void)out_size;
    const float* x    = (const float*)d_in[0];
    const float* W_ih = (const float*)d_in[1];
    const float* W_hh = (const float*)d_in[2];
    const float* b_ih = (const float*)d_in[3];
    const float* b_hh = (const float*)d_in[4];
    const float* W_fc = (const float*)d_in[5];
    const float* b_fc = (const float*)d_in[6];
    float* out = (float*)d_out;

    static bool attr_set = false;
    if (!attr_set) {
        cudaFuncSetAttribute(lstm_persistent_kernel,
                             cudaFuncAttributeMaxDynamicSharedMemorySize,
                             SMEM_BYTES);
        attr_set = true;
    }

    lstm_init_kernel<<<(NFLAGS + 255) / 256, 256>>>();
    lstm_persistent_kernel<<<NCTA, NTHR, SMEM_BYTES>>>(x, W_ih, W_hh, b_ih, b_hh,
                                                       W_fc, b_fc, out);
}

// round 17
// speedup vs baseline: 1.6783x; 1.6783x over previous
#include <cuda_runtime.h>
#include <cuda_bf16.h>

// SimpleLSTM: B=64, T=2048, H=512.
// Persistent kernel: 128 CTAs = 4 batch-groups x 32 hidden-groups.
// Identical structure to the 9826us R3 kernel (coarse single-poller sync,
// cooperative staging, 8-deep reduce, separate fc) EXCEPT the GEMM lane tile:
// lane owns rows {l, 32+l} x all 8 batch-pairs, so h loads are warp-uniform
// (broadcast, ~1 cyc) and W loads are 2 stride-1 LDS.32 -> SMEM crossbar
// drops from ~6144 to ~3072 cyc/SM/step, below the FFMA2 floor.

#define B_    64
#define T_    2048
#define H_    512
#define NCTA  128
#define NTHR  256
#define BS_   16    // batches per CTA
#define HS_   16    // hidden units per CTA
#define ROWS  64    // gate rows per CTA

// shared memory float offsets
#define OFF_W    0            // [512][64]     32768 floats (128 KB), slot = row
#define OFF_H    32768        // [512][16]      8192 floats (32 KB)
#define OFF_RED  40960        // [8][8][64] f2  8192 floats (32 KB)
#define OFF_WIH  49152        // [64]
#define OFF_BIAS 49216        // [64]
#define OFF_XT   49280        // [16]
#define SMEM_FLOATS 49312
#define SMEM_BYTES  (SMEM_FLOATS * 4)

#define FLAGSTR 32            // 128B stride between counters

// full h history, layout [t][unit][batch] (transposed for coalesced staging)
__device__ float    g_hall[(size_t)T_ * H_ * B_];
__device__ unsigned g_done[(T_ + 1) * 4 * FLAGSTR];

typedef unsigned long long ull;

__device__ __forceinline__ ull dup2(float x) {
    ull r; unsigned u = __float_as_uint(x);
    asm("mov.b64 %0, {%1, %1};" : "=l"(r) : "r"(u));
    return r;
}
__device__ __forceinline__ void fma2(ull& d, ull a, ull b) {
    asm("fma.rn.f32x2 %0, %1, %2, %0;" : "+l"(d) : "l"(a), "l"(b));
}
__device__ __forceinline__ float sigm(float x) {
    return __fdividef(1.0f, 1.0f + __expf(-x));
}
__device__ __forceinline__ float tanh_f(float x) {
    return __fdividef(2.0f, 1.0f + __expf(-2.0f * x)) - 1.0f;
}

__global__ void lstm_init_kernel() {
    int i = blockIdx.x * blockDim.x + threadIdx.x;
    if (i < (T_ + 1) * 4 * FLAGSTR) g_done[i] = 0u;
}

__global__ void __launch_bounds__(NTHR, 1)
lstm_persistent_kernel(const float* __restrict__ x,
                       const float* __restrict__ W_ih,
                       const float* __restrict__ W_hh,
                       const float* __restrict__ b_ih,
                       const float* __restrict__ b_hh,
                       float* __restrict__ out) {
    extern __shared__ float sm[];
    float* sm_W    = sm + OFF_W;             // [k][64 rows], slot = local row
    float* sm_H    = sm + OFF_H;             // [k][16 batches]
    ull*   sm_red  = (ull*)(sm + OFF_RED);   // [8 warps][8 pairs][64 rows]
    float* sm_redf = sm + OFF_RED;
    float* sm_wih  = sm + OFF_WIH;
    float* sm_bias = sm + OFF_BIAS;
    float* sm_xt   = sm + OFF_XT;

    const int tid   = threadIdx.x;
    const int cta   = blockIdx.x;
    const int gh    = cta >> 2;           // hidden group 0..31
    const int gb    = cta & 3;            // batch group 0..3
    const int unit0 = gh * HS_;
    const int b0    = gb * BS_;

    const int w    = tid >> 5;            // warp 0..7 -> K slice [w*64, w*64+64)
    const int lane = tid & 31;            // owns local rows {lane, 32+lane}

    const int j  = tid & 15;              // elementwise: hidden unit local
    const int bb = tid >> 4;              // elementwise: batch local
    const int bp = bb >> 1;               // batch-pair
    const int bc = bb & 1;                // component within pair

    // ---- one-time preload: W slice, slot s = local row s = g*16 + jj ----
    for (int idx = tid; idx < ROWS * H_; idx += NTHR) {
        int s = idx >> 9;                 // local row 0..63
        int k = idx & 511;
        int G = ((s >> 4) << 9) + unit0 + (s & 15);
        sm_W[k * 64 + s] = W_hh[(size_t)G * H_ + k];
    }
    if (tid < ROWS) {
        int G = ((tid >> 4) << 9) + unit0 + (tid & 15);
        sm_wih[tid]  = W_ih[G];
        sm_bias[tid] = b_ih[G] + b_hh[G];
    }
    __syncthreads();

    float c_reg = 0.0f;

    const float* Wk = sm_W + (w * 64) * 64;
    const float* Hk = sm_H + (w * 64) * 16;

    for (int t = 0; t < T_; ++t) {
        // ---- wait until the 32 CTAs of this batch-group published h_{t-1} ----
        if (t > 0 && tid == 0) {
            const unsigned* f = g_done + ((t << 2) + gb) * FLAGSTR;
            unsigned v;
            do {
                asm volatile("ld.acquire.gpu.global.u32 %0, [%1];"
                             : "=r"(v) : "l"(f) : "memory");
            } while (v < 32u);
        }
        __syncthreads();

        // ---- stage x_t and h slice [512][16] ----
        if (tid < BS_) sm_xt[tid] = __ldg(&x[(b0 + tid) * T_ + t]);
        if (t == 0) {
            for (int i = tid; i < H_ * BS_; i += NTHR) sm_H[i] = 0.0f;
        } else {
            const float* hsrc = g_hall + (size_t)(t - 1) * H_ * B_;
#pragma unroll
            for (int it = 0; it < 8; ++it) {
                int id = tid + it * NTHR;        // 0..2047 float4 chunks
                int k  = id >> 2;
                int cc = id & 3;
                float4 v = __ldcg((const float4*)(hsrc + k * B_ + b0 + cc * 4));
                *(float4*)(sm_H + k * 16 + cc * 4) = v;
            }
        }
        __syncthreads();

        // ---- GEMM partials: rows {lane, 32+lane} x 8 pairs, K-slice 64 ----
        // h loads are warp-uniform (broadcast); W loads stride-1 LDS.32.
        ull accA[8], accB[8];
#pragma unroll
        for (int p = 0; p < 8; ++p) { accA[p] = 0ull; accB[p] = 0ull; }

#pragma unroll 4
        for (int kk = 0; kk < 64; ++kk) {
            float wa = Wk[kk * 64 + lane];
            float wb = Wk[kk * 64 + 32 + lane];
            ulonglong2 h01 = *(const ulonglong2*)(Hk + kk * 16);
            ulonglong2 h23 = *(const ulonglong2*)(Hk + kk * 16 + 4);
            ulonglong2 h45 = *(const ulonglong2*)(Hk + kk * 16 + 8);
            ulonglong2 h67 = *(const ulonglong2*)(Hk + kk * 16 + 12);
            ull wA = dup2(wa), wB = dup2(wb);
            fma2(accA[0], wA, h01.x); fma2(accA[1], wA, h01.y);
            fma2(accA[2], wA, h23.x); fma2(accA[3], wA, h23.y);
            fma2(accA[4], wA, h45.x); fma2(accA[5], wA, h45.y);
            fma2(accA[6], wA, h67.x); fma2(accA[7], wA, h67.y);
            fma2(accB[0], wB, h01.x); fma2(accB[1], wB, h01.y);
            fma2(accB[2], wB, h23.x); fma2(accB[3], wB, h23.y);
            fma2(accB[4], wB, h45.x); fma2(accB[5], wB, h45.y);
            fma2(accB[6], wB, h67.x); fma2(accB[7], wB, h67.y);
        }

        // store partials: stride-1 across lanes -> conflict-free
#pragma unroll
        for (int p = 0; p < 8; ++p) {
            sm_red[w * 512 + p * 64 + lane]      = accA[p];
            sm_red[w * 512 + p * 64 + 32 + lane] = accB[p];
        }
        __syncthreads();

        // ---- reduce 8 K-slices + cell update (thread owns (bb, j)) ----
        float gate[4];
#pragma unroll
        for (int g = 0; g < 4; ++g) {
            int row = (g << 4) + j;
            const float* rp = sm_redf + bp * 128 + row * 2 + bc;
            float s = 0.0f;
#pragma unroll
            for (int ww = 0; ww < 8; ++ww) s += rp[ww * 1024];
            gate[g] = s + sm_xt[bb] * sm_wih[row] + sm_bias[row];
        }
        float ig = sigm(gate[0]);
        float fg = sigm(gate[1]);
        float gg = tanh_f(gate[2]);
        float og = sigm(gate[3]);
        c_reg = fg * c_reg + ig * gg;
        float h = og * tanh_f(c_reg);

        __stcg(&g_hall[((size_t)t * H_ + unit0 + j) * B_ + b0 + bb], h);
        if (t == T_ - 1) {
            out[B_ * T_ + (b0 + bb) * H_ + unit0 + j]            = h;      // h_n
            out[B_ * T_ + B_ * H_ + (b0 + bb) * H_ + unit0 + j]  = c_reg;  // c_n
        }

        __syncthreads();
        if (tid == 0) {
            __threadfence();
            unsigned* f = g_done + (((t + 1) << 2) + gb) * FLAGSTR;
            asm volatile("red.relaxed.gpu.global.add.u32 [%0], %1;"
                         :: "l"(f), "r"(1u) : "memory");
        }
    }
}

// y[b,t] = b_fc + sum_u h[t][u][b] * W_fc[u]
__global__ void fc_kernel(const float* __restrict__ W_fc,
                          const float* __restrict__ b_fc,
                          float* __restrict__ out) {
    int i = blockIdx.x * blockDim.x + threadIdx.x;   // 0..131071
    int b = i & (B_ - 1);
    int t = i >> 6;
    const float* hp = g_hall + (size_t)t * H_ * B_ + b;
    float s = 0.0f;
#pragma unroll 8
    for (int u = 0; u < H_; ++u) s += hp[u * B_] * __ldg(&W_fc[u]);
    out[b * T_ + t] = s + __ldg(&b_fc[0]);
}

extern "C" void kernel_launch(void* const* d_in, const int* in_sizes, int n_in,
                              void* d_out, int out_size) {
    (void)in_sizes; (void)n_in; (void)out_size;
    const float* x    = (const float*)d_in[0];
    const float* W_ih = (const float*)d_in[1];
    const float* W_hh = (const float*)d_in[2];
    const float* b_ih = (const float*)d_in[3];
    const float* b_hh = (const float*)d_in[4];
    const float* W_fc = (const float*)d_in[5];
    const float* b_fc = (const float*)d_in[6];
    float* out = (float*)d_out;

    static bool attr_set = false;
    if (!attr_set) {
        cudaFuncSetAttribute(lstm_persistent_kernel,
                             cudaFuncAttributeMaxDynamicSharedMemorySize,
                             SMEM_BYTES);
        attr_set = true;
    }

    lstm_init_kernel<<<((T_ + 1) * 4 * FLAGSTR + 255) / 256, 256>>>();
    lstm_persistent_kernel<<<NCTA, NTHR, SMEM_BYTES>>>(x, W_ih, W_hh, b_ih, b_hh, out);
    fc_kernel<<<(B_ * T_) / 256, 256>>>(W_fc, b_fc, out);
}